// round 6
// baseline (speedup 1.0000x reference)
#include <cuda_runtime.h>
#include <cuda_fp16.h>
#include <mma.h>

#define BB 4
#define TT 4096
#define SS 4096
#define DD 64
#define NITER 8
#define NTCH 32            // t-chunks for v_pass partials
#define TCH (TT/NTCH)      // 128 rows per chunk

// Scratch (no cudaMalloc allowed): 128MB K cache + duals + partials
__device__ __half g_K[(size_t)BB*TT*SS];
__device__ float  g_u[BB*TT];
__device__ float  g_v[BB*SS];
__device__ float  g_part[(size_t)BB*NTCH*SS];

// ---------------------------------------------------------------------------
// K[b][t][s] = valid ? exp(-dist2/(eps+1e-8)) : 0   (fp16)
// masks arrive as int32 (bool lowered by the harness)
// ---------------------------------------------------------------------------
__global__ void build_k(const float2* __restrict__ slocs,
                        const float2* __restrict__ tlocs,
                        const int* __restrict__ smask,
                        const int* __restrict__ tmask) {
    int t = blockIdx.x, b = blockIdx.y;
    float2 tl = tlocs[b*TT + t];
    bool tm = tmask[b*TT + t] != 0;
    const float inv_eps = 1.0f / (0.01f + 1e-8f);
    const float2* sl = slocs + (size_t)b*SS;
    const int* sm = smask + (size_t)b*SS;
    __half2* out = (__half2*)(g_K + ((size_t)(b*TT + t))*SS);
    for (int j = threadIdx.x; j < SS/2; j += blockDim.x) {
        int s = 2*j;
        float2 p0 = sl[s], p1 = sl[s+1];
        float dx0 = tl.x - p0.x, dy0 = tl.y - p0.y;
        float dx1 = tl.x - p1.x, dy1 = tl.y - p1.y;
        float d0 = dx0*dx0 + dy0*dy0;
        float d1 = dx1*dx1 + dy1*dy1;
        float k0 = (tm && sm[s]   != 0 && d0 < 0.04f) ? __expf(-d0*inv_eps) : 0.0f;
        float k1 = (tm && sm[s+1] != 0 && d1 < 0.04f) ? __expf(-d1*inv_eps) : 0.0f;
        out[j] = __floats2half2_rn(k0, k1);
    }
}

__global__ void init_v() {
    int i = blockIdx.x*blockDim.x + threadIdx.x;
    if (i < BB*SS) g_v[i] = 1.0f;
}

// ---------------------------------------------------------------------------
// u[t] = 1 / sum_s K[t,s]*v[s]   (one block per row; K streamed via __ldcs)
// ---------------------------------------------------------------------------
__global__ void u_pass() {
    int t = blockIdx.x, b = blockIdx.y;
    const uint4*  row = (const uint4*)(g_K + ((size_t)(b*TT + t))*SS); // 512 uint4
    const float4* v   = (const float4*)(g_v + b*SS);
    float acc = 0.0f;
    for (int j = threadIdx.x; j < SS/8; j += blockDim.x) {
        uint4 kk = __ldcs(row + j);
        float4 v0 = v[2*j], v1 = v[2*j + 1];
        float2 f0 = __half22float2(*(__half2*)&kk.x);
        float2 f1 = __half22float2(*(__half2*)&kk.y);
        float2 f2 = __half22float2(*(__half2*)&kk.z);
        float2 f3 = __half22float2(*(__half2*)&kk.w);
        acc += f0.x*v0.x + f0.y*v0.y + f1.x*v0.z + f1.y*v0.w
             + f2.x*v1.x + f2.y*v1.y + f3.x*v1.z + f3.y*v1.w;
    }
    // block reduce (256 threads = 8 warps)
    for (int o = 16; o; o >>= 1) acc += __shfl_down_sync(0xffffffffu, acc, o);
    __shared__ float red[8];
    if ((threadIdx.x & 31) == 0) red[threadIdx.x >> 5] = acc;
    __syncthreads();
    if (threadIdx.x < 8) {
        float s2 = red[threadIdx.x];
        for (int o = 4; o; o >>= 1) s2 += __shfl_down_sync(0xffu, s2, o);
        if (threadIdx.x == 0)
            g_u[b*TT + t] = (s2 > 0.0f) ? 1.0f/s2 : 0.0f;  // u==0 <=> no source
    }
}

// ---------------------------------------------------------------------------
// partial col sums: part[b][tc][s] = sum_{t in chunk} K[t,s]*u[t]
// ---------------------------------------------------------------------------
__global__ void v_pass() {
    int b = blockIdx.z, tc = blockIdx.y, sc = blockIdx.x;
    int s0 = sc*1024 + threadIdx.x*4;
    const float* u = g_u + b*TT + tc*TCH;
    const __half* base = g_K + ((size_t)(b*TT + tc*TCH))*SS + s0;
    float a0=0.f, a1=0.f, a2=0.f, a3=0.f;
    #pragma unroll 4
    for (int i = 0; i < TCH; i++) {
        uint2 kk = __ldcs((const uint2*)(base + (size_t)i*SS));
        float uu = u[i];
        float2 f0 = __half22float2(*(__half2*)&kk.x);
        float2 f1 = __half22float2(*(__half2*)&kk.y);
        a0 += f0.x*uu; a1 += f0.y*uu; a2 += f1.x*uu; a3 += f1.y*uu;
    }
    *(float4*)(g_part + ((size_t)(b*NTCH + tc))*SS + s0) = make_float4(a0,a1,a2,a3);
}

__global__ void fin_v() {
    int idx = blockIdx.x*blockDim.x + threadIdx.x;  // BB*SS
    if (idx >= BB*SS) return;
    int b = idx / SS, s = idx - b*SS;
    float sum = 0.0f;
    #pragma unroll
    for (int c = 0; c < NTCH; c++)
        sum += __ldcs(&g_part[((size_t)(b*NTCH + c))*SS + s]);
    g_v[idx] = (sum > 0.0f) ? 1.0f/sum : 0.0f;
}

// ---------------------------------------------------------------------------
// out[b][t][d] = gate(t) * u[t] * sum_s K[t,s] * v[s] * feats[b][s][d]
// wmma fp16 GEMM, fp32 accumulate. Block: 128 t x 64 d, 8 warps.
// ---------------------------------------------------------------------------
#define GBT 128
#define GBS 32
using namespace nvcuda;

__global__ void __launch_bounds__(256, 2)
gemm_out(const float* __restrict__ feats,
         const int* __restrict__ tmask,
         float* __restrict__ out) {
    __shared__ __align__(16) __half sK[GBT][GBS + 8];   // A: [t][s], ld=40
    __shared__ __align__(16) __half sW[GBS][DD + 8];    // B: [s][d], ld=72
    __shared__ __align__(16) float  sO[GBT][DD];        // epilogue staging

    int b  = blockIdx.y;
    int t0 = blockIdx.x * GBT;
    int warp = threadIdx.x >> 5;
    int wt = warp >> 1;       // 0..3  -> t offset wt*32
    int wd = warp & 1;        // 0..1  -> d offset wd*32

    wmma::fragment<wmma::accumulator,16,16,16,float> c[2][2];
    #pragma unroll
    for (int i = 0; i < 2; i++)
        #pragma unroll
        for (int j = 0; j < 2; j++)
            wmma::fill_fragment(c[i][j], 0.0f);

    for (int sc = 0; sc < SS/GBS; sc++) {
        int s0 = sc * GBS;
        // stage K tile (half2 loads, coalesced)
        for (int idx = threadIdx.x; idx < GBT*GBS/2; idx += 256) {
            int t = idx >> 4, c2 = idx & 15;
            unsigned int kk = __ldcs((const unsigned int*)
                (g_K + ((size_t)(b*TT + t0 + t))*SS + s0 + 2*c2));
            *(unsigned int*)(&sK[t][2*c2]) = kk;
        }
        // stage W tile = v[s] * feats[s][:]  (fp32 -> fp16)
        for (int idx = threadIdx.x; idx < GBS*DD/4; idx += 256) {
            int s = idx >> 4, c4 = idx & 15;
            float4 f = *(const float4*)(feats + ((size_t)(b*SS + s0 + s))*DD + 4*c4);
            float vv = g_v[b*SS + s0 + s];
            *(__half2*)(&sW[s][4*c4    ]) = __floats2half2_rn(f.x*vv, f.y*vv);
            *(__half2*)(&sW[s][4*c4 + 2]) = __floats2half2_rn(f.z*vv, f.w*vv);
        }
        __syncthreads();
        #pragma unroll
        for (int kk = 0; kk < GBS; kk += 16) {
            wmma::fragment<wmma::matrix_a,16,16,16,__half,wmma::row_major> a[2];
            wmma::fragment<wmma::matrix_b,16,16,16,__half,wmma::row_major> bf[2];
            wmma::load_matrix_sync(a[0],  &sK[wt*32     ][kk], GBS + 8);
            wmma::load_matrix_sync(a[1],  &sK[wt*32 + 16][kk], GBS + 8);
            wmma::load_matrix_sync(bf[0], &sW[kk][wd*32     ], DD + 8);
            wmma::load_matrix_sync(bf[1], &sW[kk][wd*32 + 16], DD + 8);
            #pragma unroll
            for (int i = 0; i < 2; i++)
                #pragma unroll
                for (int j = 0; j < 2; j++)
                    wmma::mma_sync(c[i][j], a[i], bf[j], c[i][j]);
        }
        __syncthreads();
    }
    // epilogue: scale rows by gate*u and write
    #pragma unroll
    for (int i = 0; i < 2; i++)
        #pragma unroll
        for (int j = 0; j < 2; j++)
            wmma::store_matrix_sync(&sO[wt*32 + i*16][wd*32 + j*16], c[i][j],
                                    DD, wmma::mem_row_major);
    __syncthreads();
    for (int idx = threadIdx.x; idx < GBT*DD/4; idx += 256) {
        int t = idx >> 4, c4 = idx & 15;
        int gt = b*TT + t0 + t;
        float scl = (tmask[gt] != 0) ? g_u[gt] : 0.0f; // g_u==0 encodes !has_source
        float4 f = *(float4*)(&sO[t][4*c4]);
        f.x *= scl; f.y *= scl; f.z *= scl; f.w *= scl;
        *(float4*)(out + ((size_t)gt)*DD + 4*c4) = f;
    }
}

// ---------------------------------------------------------------------------
extern "C" void kernel_launch(void* const* d_in, const int* in_sizes, int n_in,
                              void* d_out, int out_size) {
    const float* feats  = (const float*)d_in[0];
    const float2* slocs = (const float2*)d_in[1];
    const float2* tlocs = (const float2*)d_in[2];
    const int* smask    = (const int*)d_in[3];   // bool -> int32 in harness
    const int* tmask    = (const int*)d_in[4];
    float* out = (float*)d_out;

    build_k<<<dim3(TT, BB), 256>>>(slocs, tlocs, smask, tmask);
    init_v<<<(BB*SS + 255)/256, 256>>>();
    for (int it = 0; it < NITER; it++) {
        u_pass<<<dim3(TT, BB), 256>>>();
        v_pass<<<dim3(SS/1024, NTCH, BB), 256>>>();
        fin_v<<<(BB*SS + 255)/256, 256>>>();
    }
    gemm_out<<<dim3(TT/GBT, BB), 256>>>(feats, tmask, out);
}

// round 13
// speedup vs baseline: 1.3559x; 1.3559x over previous
#include <cuda_runtime.h>
#include <cuda_fp16.h>
#include <mma.h>

#define BB 4
#define TT 4096
#define SS 4096
#define DD 64
#define NITER 8
#define CAP 1024           // max nnz per row/col (expected ~515, max ~620)

// Scratch: dense K (for GEMM) + CSR/CSC compacted K (for Sinkhorn passes)
__device__ __half        g_K[(size_t)BB*TT*SS];      // 128 MB dense (GEMM only)
__device__ unsigned int  g_csr[(size_t)BB*TT*CAP];   // (s<<16)|half bits
__device__ unsigned int  g_csc[(size_t)BB*SS*CAP];   // (t<<16)|half bits
__device__ int           g_rlen[BB*TT];
__device__ int           g_clen[BB*SS];
__device__ float         g_u[BB*TT];
__device__ float         g_v[BB*SS];

// ---------------------------------------------------------------------------
// init: zero CSC counters, v = 1
// ---------------------------------------------------------------------------
__global__ void init0() {
    int i = blockIdx.x*blockDim.x + threadIdx.x;
    if (i < BB*SS) { g_clen[i] = 0; g_v[i] = 1.0f; }
}

// ---------------------------------------------------------------------------
// build: dense K + CSR (ballot-compacted) + CSC (atomic scatter)
// one block per (t,b) row, 256 threads
// ---------------------------------------------------------------------------
__global__ void build_k(const float2* __restrict__ slocs,
                        const float2* __restrict__ tlocs,
                        const int* __restrict__ smask,
                        const int* __restrict__ tmask) {
    int t = blockIdx.x, b = blockIdx.y;
    int lane = threadIdx.x & 31;
    float2 tl = tlocs[b*TT + t];
    bool tm = tmask[b*TT + t] != 0;
    const float inv_eps = 1.0f / (0.01f + 1e-8f);
    const float2* sl = slocs + (size_t)b*SS;
    const int* sm = smask + (size_t)b*SS;
    __half* dense = g_K + ((size_t)(b*TT + t))*SS;
    unsigned int* row = g_csr + ((size_t)(b*TT + t))*CAP;

    __shared__ int cnt;
    if (threadIdx.x == 0) cnt = 0;
    __syncthreads();

    for (int s = threadIdx.x; s < SS; s += 256) {
        float2 p = sl[s];
        float dx = tl.x - p.x, dy = tl.y - p.y;
        float d = dx*dx + dy*dy;
        bool valid = tm && (sm[s] != 0) && (d < 0.04f);
        float k = valid ? __expf(-d*inv_eps) : 0.0f;
        __half kh = __float2half_rn(k);
        dense[s] = kh;
        unsigned short kb = __half_as_ushort(kh);
        // CSR append: warp-aggregated
        unsigned int m = __ballot_sync(0xffffffffu, valid);
        int base = 0;
        if (lane == 0 && m) base = atomicAdd(&cnt, __popc(m));
        base = __shfl_sync(0xffffffffu, base, 0);
        if (valid) {
            int off = base + __popc(m & ((1u << lane) - 1u));
            if (off < CAP) row[off] = ((unsigned)s << 16) | kb;
            // CSC scatter
            int slot = atomicAdd(&g_clen[b*SS + s], 1);
            if (slot < CAP)
                g_csc[((size_t)(b*SS + s))*CAP + slot] = ((unsigned)t << 16) | kb;
        }
    }
    __syncthreads();
    if (threadIdx.x == 0) g_rlen[b*TT + t] = (cnt < CAP) ? cnt : CAP;
}

// ---------------------------------------------------------------------------
// u[t] = 1 / sum_{s in row t} K * v[s]      (one warp per row)
// ---------------------------------------------------------------------------
__global__ void u_sparse() {
    int b = blockIdx.y;
    int r = blockIdx.x*8 + (threadIdx.x >> 5);
    int lane = threadIdx.x & 31;
    int n = g_rlen[b*TT + r];
    const unsigned int* row = g_csr + ((size_t)(b*TT + r))*CAP;
    const float* v = g_v + b*SS;
    float acc = 0.0f;
    for (int i = lane; i < n; i += 32) {
        unsigned int p = row[i];
        acc += __half2float(__ushort_as_half((unsigned short)(p & 0xffffu))) * v[p >> 16];
    }
    for (int o = 16; o; o >>= 1) acc += __shfl_down_sync(0xffffffffu, acc, o);
    if (lane == 0)
        g_u[b*TT + r] = (acc > 0.0f) ? 1.0f/acc : 0.0f;   // u==0 <=> no source
}

// ---------------------------------------------------------------------------
// v[s] = 1 / sum_{t in col s} K * u[t]      (one warp per column)
// ---------------------------------------------------------------------------
__global__ void v_sparse() {
    int b = blockIdx.y;
    int c = blockIdx.x*8 + (threadIdx.x >> 5);
    int lane = threadIdx.x & 31;
    int n = g_clen[b*SS + c];
    if (n > CAP) n = CAP;
    const unsigned int* col = g_csc + ((size_t)(b*SS + c))*CAP;
    const float* u = g_u + b*TT;
    float acc = 0.0f;
    for (int i = lane; i < n; i += 32) {
        unsigned int p = col[i];
        acc += __half2float(__ushort_as_half((unsigned short)(p & 0xffffu))) * u[p >> 16];
    }
    for (int o = 16; o; o >>= 1) acc += __shfl_down_sync(0xffffffffu, acc, o);
    if (lane == 0)
        g_v[b*SS + c] = (acc > 0.0f) ? 1.0f/acc : 0.0f;
}

// ---------------------------------------------------------------------------
// out[b][t][d] = gate(t) * u[t] * sum_s K[t,s] * v[s] * feats[b][s][d]
// dense wmma fp16 GEMM, fp32 accumulate (K nonzeros uniformly scattered)
// ---------------------------------------------------------------------------
#define GBT 128
#define GBS 32
using namespace nvcuda;

__global__ void __launch_bounds__(256, 2)
gemm_out(const float* __restrict__ feats,
         const int* __restrict__ tmask,
         float* __restrict__ out) {
    __shared__ __align__(16) __half sK[GBT][GBS + 8];   // A: [t][s], ld=40
    __shared__ __align__(16) __half sW[GBS][DD + 8];    // B: [s][d], ld=72
    __shared__ __align__(16) float  sO[GBT][DD];        // epilogue staging

    int b  = blockIdx.y;
    int t0 = blockIdx.x * GBT;
    int warp = threadIdx.x >> 5;
    int wt = warp >> 1;
    int wd = warp & 1;

    wmma::fragment<wmma::accumulator,16,16,16,float> c[2][2];
    #pragma unroll
    for (int i = 0; i < 2; i++)
        #pragma unroll
        for (int j = 0; j < 2; j++)
            wmma::fill_fragment(c[i][j], 0.0f);

    for (int sc = 0; sc < SS/GBS; sc++) {
        int s0 = sc * GBS;
        for (int idx = threadIdx.x; idx < GBT*GBS/2; idx += 256) {
            int t = idx >> 4, c2 = idx & 15;
            unsigned int kk = __ldcs((const unsigned int*)
                (g_K + ((size_t)(b*TT + t0 + t))*SS + s0 + 2*c2));
            *(unsigned int*)(&sK[t][2*c2]) = kk;
        }
        for (int idx = threadIdx.x; idx < GBS*DD/4; idx += 256) {
            int s = idx >> 4, c4 = idx & 15;
            float4 f = *(const float4*)(feats + ((size_t)(b*SS + s0 + s))*DD + 4*c4);
            float vv = g_v[b*SS + s0 + s];
            *(__half2*)(&sW[s][4*c4    ]) = __floats2half2_rn(f.x*vv, f.y*vv);
            *(__half2*)(&sW[s][4*c4 + 2]) = __floats2half2_rn(f.z*vv, f.w*vv);
        }
        __syncthreads();
        #pragma unroll
        for (int kk = 0; kk < GBS; kk += 16) {
            wmma::fragment<wmma::matrix_a,16,16,16,__half,wmma::row_major> a[2];
            wmma::fragment<wmma::matrix_b,16,16,16,__half,wmma::row_major> bf[2];
            wmma::load_matrix_sync(a[0],  &sK[wt*32     ][kk], GBS + 8);
            wmma::load_matrix_sync(a[1],  &sK[wt*32 + 16][kk], GBS + 8);
            wmma::load_matrix_sync(bf[0], &sW[kk][wd*32     ], DD + 8);
            wmma::load_matrix_sync(bf[1], &sW[kk][wd*32 + 16], DD + 8);
            #pragma unroll
            for (int i = 0; i < 2; i++)
                #pragma unroll
                for (int j = 0; j < 2; j++)
                    wmma::mma_sync(c[i][j], a[i], bf[j], c[i][j]);
        }
        __syncthreads();
    }
    #pragma unroll
    for (int i = 0; i < 2; i++)
        #pragma unroll
        for (int j = 0; j < 2; j++)
            wmma::store_matrix_sync(&sO[wt*32 + i*16][wd*32 + j*16], c[i][j],
                                    DD, wmma::mem_row_major);
    __syncthreads();
    for (int idx = threadIdx.x; idx < GBT*DD/4; idx += 256) {
        int t = idx >> 4, c4 = idx & 15;
        int gt = b*TT + t0 + t;
        float scl = (tmask[gt] != 0) ? g_u[gt] : 0.0f;  // g_u==0 encodes !has_source
        float4 f = *(float4*)(&sO[t][4*c4]);
        f.x *= scl; f.y *= scl; f.z *= scl; f.w *= scl;
        *(float4*)(out + ((size_t)gt)*DD + 4*c4) = f;
    }
}

// ---------------------------------------------------------------------------
extern "C" void kernel_launch(void* const* d_in, const int* in_sizes, int n_in,
                              void* d_out, int out_size) {
    const float* feats  = (const float*)d_in[0];
    const float2* slocs = (const float2*)d_in[1];
    const float2* tlocs = (const float2*)d_in[2];
    const int* smask    = (const int*)d_in[3];   // bool -> int32 in harness
    const int* tmask    = (const int*)d_in[4];
    float* out = (float*)d_out;

    init0<<<(BB*SS + 255)/256, 256>>>();
    build_k<<<dim3(TT, BB), 256>>>(slocs, tlocs, smask, tmask);
    for (int it = 0; it < NITER; it++) {
        u_sparse<<<dim3(TT/8, BB), 256>>>();
        v_sparse<<<dim3(SS/8, BB), 256>>>();
    }
    gemm_out<<<dim3(TT/GBT, BB), 256>>>(feats, tmask, out);
}

// round 14
// speedup vs baseline: 1.5686x; 1.1569x over previous
#include <cuda_runtime.h>
#include <cuda_fp16.h>
#include <mma.h>

#define BB 4
#define TT 4096
#define SS 4096
#define DD 64
#define NITER 8
#define CAP 1024           // max nnz per row/col (expected ~515, max ~620)

__device__ __half        g_K[(size_t)BB*TT*SS];      // 128 MB dense (GEMM only)
__device__ unsigned int  g_csr[(size_t)BB*TT*CAP];   // (s<<16)|half bits
__device__ unsigned int  g_csc[(size_t)BB*SS*CAP];   // (t<<16)|half bits
__device__ int           g_rlen[BB*TT];
__device__ int           g_clen[BB*SS];
__device__ float         g_u[BB*TT];
__device__ float         g_v[BB*SS];

// ---------------------------------------------------------------------------
__global__ void init0() {
    int i = blockIdx.x*blockDim.x + threadIdx.x;
    if (i < BB*SS) { g_clen[i] = 0; g_v[i] = 1.0f; }
}

__global__ void zero_out(float* __restrict__ out) {
    int i = blockIdx.x*blockDim.x + threadIdx.x;   // 262144 float4 = 1M floats
    ((float4*)out)[i] = make_float4(0.f,0.f,0.f,0.f);
}

// ---------------------------------------------------------------------------
// build: dense K (half2) + CSR (dual-ballot append) + CSC (atomic scatter)
// one block per (t,b) row, 256 threads, 2 sources per thread-iteration
// ---------------------------------------------------------------------------
__global__ void build_k(const float2* __restrict__ slocs,
                        const float2* __restrict__ tlocs,
                        const int* __restrict__ smask,
                        const int* __restrict__ tmask) {
    int t = blockIdx.x, b = blockIdx.y;
    int lane = threadIdx.x & 31;
    unsigned lmask = (1u << lane) - 1u;
    float2 tl = tlocs[b*TT + t];
    bool tm = tmask[b*TT + t] != 0;
    const float inv_eps = 1.0f / (0.01f + 1e-8f);
    const float2* sl = slocs + (size_t)b*SS;
    const int* sm = smask + (size_t)b*SS;
    __half2* dense = (__half2*)(g_K + ((size_t)(b*TT + t))*SS);
    unsigned int* row = g_csr + ((size_t)(b*TT + t))*CAP;

    __shared__ int cnt;
    if (threadIdx.x == 0) cnt = 0;
    __syncthreads();

    for (int j = threadIdx.x; j < SS/2; j += 256) {   // uniform 8 iterations
        int s = 2*j;
        float4 pp = *(const float4*)(sl + s);          // two float2 points
        int2 mm = *(const int2*)(sm + s);
        float dx0 = tl.x - pp.x, dy0 = tl.y - pp.y;
        float dx1 = tl.x - pp.z, dy1 = tl.y - pp.w;
        float d0 = dx0*dx0 + dy0*dy0;
        float d1 = dx1*dx1 + dy1*dy1;
        bool v0 = tm && (mm.x != 0) && (d0 < 0.04f);
        bool v1 = tm && (mm.y != 0) && (d1 < 0.04f);
        float k0 = v0 ? __expf(-d0*inv_eps) : 0.0f;
        float k1 = v1 ? __expf(-d1*inv_eps) : 0.0f;
        __half h0 = __float2half_rn(k0), h1 = __float2half_rn(k1);
        dense[j] = __halves2half2(h0, h1);

        unsigned m0 = __ballot_sync(0xffffffffu, v0);
        unsigned m1 = __ballot_sync(0xffffffffu, v1);
        int tot = __popc(m0) + __popc(m1);
        int base = 0;
        if (lane == 0 && tot) base = atomicAdd(&cnt, tot);
        base = __shfl_sync(0xffffffffu, base, 0);
        if (v0) {
            int off = base + __popc(m0 & lmask);
            unsigned short kb = __half_as_ushort(h0);
            if (off < CAP) row[off] = ((unsigned)s << 16) | kb;
            int slot = atomicAdd(&g_clen[b*SS + s], 1);
            if (slot < CAP)
                g_csc[((size_t)(b*SS + s))*CAP + slot] = ((unsigned)t << 16) | kb;
        }
        if (v1) {
            int off = base + __popc(m0) + __popc(m1 & lmask);
            unsigned short kb = __half_as_ushort(h1);
            if (off < CAP) row[off] = ((unsigned)(s+1) << 16) | kb;
            int slot = atomicAdd(&g_clen[b*SS + s + 1], 1);
            if (slot < CAP)
                g_csc[((size_t)(b*SS + s + 1))*CAP + slot] = ((unsigned)t << 16) | kb;
        }
    }
    __syncthreads();
    if (threadIdx.x == 0) g_rlen[b*TT + t] = (cnt < CAP) ? cnt : CAP;
}

// ---------------------------------------------------------------------------
// u[t] = 1 / sum_{row t} K*v[s]   one warp per row; uint4 = 4 entries/lane
// ---------------------------------------------------------------------------
__global__ void u_sparse() {
    int b = blockIdx.y;
    int r = blockIdx.x*8 + (threadIdx.x >> 5);
    int lane = threadIdx.x & 31;
    int n = g_rlen[b*TT + r];
    const uint4* row = (const uint4*)(g_csr + ((size_t)(b*TT + r))*CAP);
    const float* v = g_v + b*SS;
    float a0=0.f, a1=0.f, a2=0.f, a3=0.f;
    int e = lane*4;
    int nit = (n + 127) >> 7;                 // 128 entries per pass, <= 8
    for (int j = 0; j < nit; j++) {
        uint4 q = row[j*32 + lane];
        if (e   < n) a0 += __half2float(__ushort_as_half((unsigned short)q.x)) * v[q.x >> 16];
        if (e+1 < n) a1 += __half2float(__ushort_as_half((unsigned short)q.y)) * v[q.y >> 16];
        if (e+2 < n) a2 += __half2float(__ushort_as_half((unsigned short)q.z)) * v[q.z >> 16];
        if (e+3 < n) a3 += __half2float(__ushort_as_half((unsigned short)q.w)) * v[q.w >> 16];
        e += 128;
    }
    float acc = (a0 + a1) + (a2 + a3);
    for (int o = 16; o; o >>= 1) acc += __shfl_down_sync(0xffffffffu, acc, o);
    if (lane == 0)
        g_u[b*TT + r] = (acc > 0.0f) ? 1.0f/acc : 0.0f;   // u==0 <=> no source
}

// ---------------------------------------------------------------------------
__global__ void v_sparse() {
    int b = blockIdx.y;
    int c = blockIdx.x*8 + (threadIdx.x >> 5);
    int lane = threadIdx.x & 31;
    int n = g_clen[b*SS + c];
    if (n > CAP) n = CAP;
    const uint4* col = (const uint4*)(g_csc + ((size_t)(b*SS + c))*CAP);
    const float* u = g_u + b*TT;
    float a0=0.f, a1=0.f, a2=0.f, a3=0.f;
    int e = lane*4;
    int nit = (n + 127) >> 7;
    for (int j = 0; j < nit; j++) {
        uint4 q = col[j*32 + lane];
        if (e   < n) a0 += __half2float(__ushort_as_half((unsigned short)q.x)) * u[q.x >> 16];
        if (e+1 < n) a1 += __half2float(__ushort_as_half((unsigned short)q.y)) * u[q.y >> 16];
        if (e+2 < n) a2 += __half2float(__ushort_as_half((unsigned short)q.z)) * u[q.z >> 16];
        if (e+3 < n) a3 += __half2float(__ushort_as_half((unsigned short)q.w)) * u[q.w >> 16];
        e += 128;
    }
    float acc = (a0 + a1) + (a2 + a3);
    for (int o = 16; o; o >>= 1) acc += __shfl_down_sync(0xffffffffu, acc, o);
    if (lane == 0)
        g_v[b*SS + c] = (acc > 0.0f) ? 1.0f/acc : 0.0f;
}

// ---------------------------------------------------------------------------
// out += gate(t)*u[t] * K[t, s-slice] * (v*feats)[s-slice]   per s-chunk CTA
// grid (TT/GBT, BB, SCH); partials combined via atomicAdd (out zeroed first)
// ---------------------------------------------------------------------------
#define GBT 128
#define GBS 32
#define SCH 8
#define SLEN (SS/SCH)      // 512
using namespace nvcuda;

__global__ void __launch_bounds__(256, 2)
gemm_out(const float* __restrict__ feats,
         const int* __restrict__ tmask,
         float* __restrict__ out) {
    __shared__ __align__(16) __half sK[GBT][GBS + 8];
    __shared__ __align__(16) __half sW[GBS][DD + 8];
    __shared__ __align__(16) float  sO[GBT][DD];

    int b  = blockIdx.y;
    int t0 = blockIdx.x * GBT;
    int sbase = blockIdx.z * SLEN;
    int warp = threadIdx.x >> 5;
    int wt = warp >> 1;
    int wd = warp & 1;

    wmma::fragment<wmma::accumulator,16,16,16,float> c[2][2];
    #pragma unroll
    for (int i = 0; i < 2; i++)
        #pragma unroll
        for (int j = 0; j < 2; j++)
            wmma::fill_fragment(c[i][j], 0.0f);

    for (int sc = 0; sc < SLEN/GBS; sc++) {
        int s0 = sbase + sc * GBS;
        for (int idx = threadIdx.x; idx < GBT*GBS/2; idx += 256) {
            int t = idx >> 4, c2 = idx & 15;
            unsigned int kk = __ldcs((const unsigned int*)
                (g_K + ((size_t)(b*TT + t0 + t))*SS + s0 + 2*c2));
            *(unsigned int*)(&sK[t][2*c2]) = kk;
        }
        for (int idx = threadIdx.x; idx < GBS*DD/4; idx += 256) {
            int s = idx >> 4, c4 = idx & 15;
            float4 f = *(const float4*)(feats + ((size_t)(b*SS + s0 + s))*DD + 4*c4);
            float vv = g_v[b*SS + s0 + s];
            *(__half2*)(&sW[s][4*c4    ]) = __floats2half2_rn(f.x*vv, f.y*vv);
            *(__half2*)(&sW[s][4*c4 + 2]) = __floats2half2_rn(f.z*vv, f.w*vv);
        }
        __syncthreads();
        #pragma unroll
        for (int kk = 0; kk < GBS; kk += 16) {
            wmma::fragment<wmma::matrix_a,16,16,16,__half,wmma::row_major> a[2];
            wmma::fragment<wmma::matrix_b,16,16,16,__half,wmma::row_major> bf[2];
            wmma::load_matrix_sync(a[0],  &sK[wt*32     ][kk], GBS + 8);
            wmma::load_matrix_sync(a[1],  &sK[wt*32 + 16][kk], GBS + 8);
            wmma::load_matrix_sync(bf[0], &sW[kk][wd*32     ], DD + 8);
            wmma::load_matrix_sync(bf[1], &sW[kk][wd*32 + 16], DD + 8);
            #pragma unroll
            for (int i = 0; i < 2; i++)
                #pragma unroll
                for (int j = 0; j < 2; j++)
                    wmma::mma_sync(c[i][j], a[i], bf[j], c[i][j]);
        }
        __syncthreads();
    }
    #pragma unroll
    for (int i = 0; i < 2; i++)
        #pragma unroll
        for (int j = 0; j < 2; j++)
            wmma::store_matrix_sync(&sO[wt*32 + i*16][wd*32 + j*16], c[i][j],
                                    DD, wmma::mem_row_major);
    __syncthreads();
    for (int idx = threadIdx.x; idx < GBT*DD/4; idx += 256) {
        int t = idx >> 4, c4 = idx & 15;
        int gt = b*TT + t0 + t;
        float scl = (tmask[gt] != 0) ? g_u[gt] : 0.0f;  // g_u==0 encodes !has_source
        float4 f = *(float4*)(&sO[t][4*c4]);
        float* o = out + ((size_t)gt)*DD + 4*c4;
        atomicAdd(o    , f.x*scl);
        atomicAdd(o + 1, f.y*scl);
        atomicAdd(o + 2, f.z*scl);
        atomicAdd(o + 3, f.w*scl);
    }
}

// ---------------------------------------------------------------------------
extern "C" void kernel_launch(void* const* d_in, const int* in_sizes, int n_in,
                              void* d_out, int out_size) {
    const float* feats  = (const float*)d_in[0];
    const float2* slocs = (const float2*)d_in[1];
    const float2* tlocs = (const float2*)d_in[2];
    const int* smask    = (const int*)d_in[3];   // bool -> int32 in harness
    const int* tmask    = (const int*)d_in[4];
    float* out = (float*)d_out;

    init0<<<(BB*SS + 255)/256, 256>>>();
    zero_out<<<(BB*TT*DD/4 + 255)/256, 256>>>(out);
    build_k<<<dim3(TT, BB), 256>>>(slocs, tlocs, smask, tmask);
    for (int it = 0; it < NITER; it++) {
        u_sparse<<<dim3(TT/8, BB), 256>>>();
        v_sparse<<<dim3(SS/8, BB), 256>>>();
    }
    gemm_out<<<dim3(TT/GBT, BB, SCH), 256>>>(feats, tmask, out);
}